// round 15
// baseline (speedup 1.0000x reference)
#include <cuda_runtime.h>
#include <math.h>

#define NXD 32
#define HID 256
#define NOUT 528
#define BM 32
#define NTHREADS 128
#define HSTR 32

// kernel-1 shared layout (float offsets), total 18432 floats = 73728 B -> 3 blocks/SM
#define OFF_H2 0        // 256*32 = 8192  (X overlays first 1024 floats)
#define OFF_X  0
#define OFF_W  8192     // 8*256 = 2048
#define OFF_H1 10240    // 256*32 = 8192
#define SMEM1_FLOATS 18432

// kernel-2: 32 samples x stride 532
#define LSTRIDE 532
#define SMEM2_FLOATS (32 * LSTRIDE)   // 17024 floats = 68096 B

// global scratch for packed L: 65536 x 528 floats = 138.4 MB
__device__ float g_L[65536ull * NOUT];

typedef unsigned long long u64;

__device__ __forceinline__ u64 pk2(float lo, float hi) {
    u64 d; asm("mov.b64 %0, {%1, %2};" : "=l"(d) : "f"(lo), "f"(hi)); return d;
}
__device__ __forceinline__ void fma2(u64& d, u64 a, u64 b) {
    asm("fma.rn.f32x2 %0, %1, %2, %0;" : "+l"(d) : "l"(a), "l"(b));
}
__device__ __forceinline__ float2 up2(u64 d) {
    float2 r; asm("mov.b64 {%0, %1}, %2;" : "=f"(r.x), "=f"(r.y) : "l"(d)); return r;
}
__device__ __forceinline__ float ftanh(float x) {
    x = fminf(fmaxf(x, -15.f), 15.f);
    float e = __expf(2.f * x);
    return __fdividef(e - 1.f, e + 1.f);
}
__device__ __forceinline__ float fsplus(float v) {
    float sp = (v > 20.f) ? v : __logf(1.f + __expf(v));
    return fminf(fmaxf(sp + 0.01f, 0.01f), 100.f);
}

// Block 32s x 256c, 4 warps. Warp wp owns cols {64wp + c + 8t : t=0..7}.
// Lane (r=tx>>3, c=tx&7): samples sbase=8r..8r+7 ; cols cb=64wp+c, stride 8.
// acc[sp][t] = f32x2 over samples (sbase+2sp, sbase+2sp+1), col cb+8t.
// MODE 0: tanh -> transposed smem outp[col*HSTR + s]   (h1/h2)
// MODE 1: G3 cols [0,256): wp==0 && t<4 -> softplus else 0.1*tanh -> global Lg
// MODE 2: G3 cols [256,512): 0.1*tanh -> global Lg (+256 offset)
template<int KTOT, int MODE>
__device__ __forceinline__ void gemm_tile(
    float* sm, const float* __restrict__ Wg, int ldw,
    const float* __restrict__ bias,
    const float* sHin, float* outp, size_t ostride,
    int sbase, int wp, int tx)
{
    const int NCH = KTOT / 8;
    const int c  = tx & 7;
    const int cb = 64 * wp + c;
    const int tid = threadIdx.x;
    float* sW = sm + OFF_W;

    u64 acc[4][8];
    #pragma unroll
    for (int t = 0; t < 8; t++) {
        float bv = __ldg(&bias[cb + 8 * t]);
        u64 bd = pk2(bv, bv);
        #pragma unroll
        for (int sp = 0; sp < 4; sp++) acc[sp][t] = bd;
    }

    float4 rg[4];
    auto stage_ld = [&](int ch) {
        #pragma unroll
        for (int rep = 0; rep < 4; rep++) {
            int idx = tid + 128 * rep;
            int row = idx >> 6, c4 = idx & 63;
            rg[rep] = *(const float4*)&Wg[(size_t)(ch * 8 + row) * ldw + 4 * c4];
        }
    };
    auto stage_st = [&]() {
        #pragma unroll
        for (int rep = 0; rep < 4; rep++) {
            int idx = tid + 128 * rep;
            int row = idx >> 6, c4 = idx & 63;
            *(float4*)&sW[row * 256 + 4 * c4] = rg[rep];
        }
    };

    stage_ld(0);
    stage_st();
    __syncthreads();

    for (int ch = 0; ch < NCH; ch++) {
        if (ch + 1 < NCH) stage_ld(ch + 1);
        #pragma unroll
        for (int kk = 0; kk < 8; kk++) {
            const float* hrow = sHin + (8 * ch + kk) * HSTR + sbase;
            ulonglong2 hA = *(const ulonglong2*)hrow;
            ulonglong2 hB = *(const ulonglong2*)(hrow + 4);
            u64 hd0 = hA.x, hd1 = hA.y, hd2 = hB.x, hd3 = hB.y;
            const float* wrow = sW + kk * 256;
            #pragma unroll
            for (int t = 0; t < 8; t++) {
                float wv = wrow[cb + 8 * t];
                u64 wd = pk2(wv, wv);
                fma2(acc[0][t], hd0, wd);
                fma2(acc[1][t], hd1, wd);
                fma2(acc[2][t], hd2, wd);
                fma2(acc[3][t], hd3, wd);
            }
        }
        __syncthreads();
        if (ch + 1 < NCH) { stage_st(); __syncthreads(); }
    }

    // epilogue
    if (MODE == 0) {
        #pragma unroll
        for (int t = 0; t < 8; t++) {
            const int col = cb + 8 * t;
            #pragma unroll
            for (int sp = 0; sp < 4; sp++) {
                float2 v = up2(acc[sp][t]);
                float2 o = { ftanh(v.x), ftanh(v.y) };
                *(float2*)&outp[col * HSTR + sbase + 2 * sp] = o;
            }
        }
    } else {
        #pragma unroll
        for (int sp = 0; sp < 4; sp++) {
            #pragma unroll
            for (int e = 0; e < 2; e++) {
                const int s = sbase + 2 * sp + e;
                float* Ls = outp + (size_t)s * ostride + ((MODE == 2) ? 256 : 0);
                #pragma unroll
                for (int t = 0; t < 8; t++) {
                    float2 v = up2(acc[sp][t]);
                    float val = e ? v.y : v.x;
                    bool dg = (MODE == 1) && (wp == 0) && (t < 4); // global col < 32
                    Ls[cb + 8 * t] = dg ? fsplus(val) : 0.1f * ftanh(val);
                }
            }
        }
    }
}

__global__ void __launch_bounds__(NTHREADS, 3) covnet_mlp_kernel(
    const float* __restrict__ P_prev,
    const float* __restrict__ W1, const float* __restrict__ b1,
    const float* __restrict__ W2, const float* __restrict__ b2,
    const float* __restrict__ W3, const float* __restrict__ b3)
{
    extern __shared__ float sm[];
    const int tid = threadIdx.x;
    const int tx = tid & 31;
    const int wp = tid >> 5;            // 0..3
    const int sbase = 8 * (tx >> 3);
    const size_t b0 = (size_t)blockIdx.x * BM;
    float* Lg = g_L + b0 * NOUT;

    // gather diagonal (transposed): sX[d*HSTR + s] = log(clip(P_prev[s,d,d]))
    for (int i = tid; i < NXD * BM; i += NTHREADS) {
        int d = i >> 5, s = i & 31;
        float v = P_prev[(b0 + (size_t)s) * 1024 + d * 33];
        sm[OFF_X + d * HSTR + s] = __logf(fmaxf(v, 1e-6f));
    }
    __syncthreads();

    gemm_tile<32,  0>(sm, W1,       HID,  b1,       sm + OFF_X,  sm + OFF_H1, 0,    sbase, wp, tx);
    gemm_tile<256, 0>(sm, W2,       HID,  b2,       sm + OFF_H1, sm + OFF_H2, 0,    sbase, wp, tx);
    gemm_tile<256, 1>(sm, W3,       NOUT, b3,       sm + OFF_H2, Lg,          NOUT, sbase, wp, tx);
    gemm_tile<256, 2>(sm, W3 + 256, NOUT, b3 + 256, sm + OFF_H2, Lg,          NOUT, sbase, wp, tx);

    // ====== GEMM3 tail: cols [512, 528) — lane s=tx, warp wp -> cols 512+4wp..+3
    {
        const int s = tx;
        float a[4];
        float4 bt = *(const float4*)&b3[512 + 4 * wp];
        a[0] = bt.x; a[1] = bt.y; a[2] = bt.z; a[3] = bt.w;
        const float* hr = sm + OFF_H2;
        #pragma unroll 8
        for (int k = 0; k < HID; k++) {
            float hv = hr[k * HSTR + s];
            float4 w = __ldg((const float4*)&W3[(size_t)k * NOUT + 512 + 4 * wp]);
            a[0] += hv * w.x; a[1] += hv * w.y;
            a[2] += hv * w.z; a[3] += hv * w.w;
        }
        float* Ls = Lg + (size_t)s * NOUT + 512 + 4 * wp;
        #pragma unroll
        for (int q = 0; q < 4; q++) Ls[q] = 0.1f * ftanh(a[q]);
    }
}

// =================== kernel 2: P = L*L^T + Q ===================
__global__ void __launch_bounds__(NTHREADS, 3) covnet_llt_kernel(
    const float* __restrict__ Q, float* __restrict__ out)
{
    extern __shared__ float sm[];
    const int tid = threadIdx.x;
    const int tx = tid & 31;
    const int wp = tid >> 5;
    const size_t b0 = (size_t)blockIdx.x * 32;

    // load 32 samples' packed L, coalesced float4
    {
        const float4* src = (const float4*)(g_L + b0 * NOUT);
        for (int idx = tid; idx < 32 * (NOUT / 4); idx += NTHREADS) {
            int s = idx / (NOUT / 4), q = idx % (NOUT / 4);
            *(float4*)&sm[s * LSTRIDE + 4 * q] = src[(size_t)s * (NOUT / 4) + q];
        }
    }
    __syncthreads();

    const int k = tx;
    float Qk[32];
    #pragma unroll
    for (int i = 0; i < 32; i++) Qk[i] = __ldg(&Q[i * 32 + k]);
    const int kb = 32 + k * (k - 1) / 2;

    #pragma unroll 1
    for (int ss = 0; ss < 8; ss++) {
        const int s = 8 * wp + ss;
        const float* Lr = sm + s * LSTRIDE;

        float Lk[32];
        #pragma unroll
        for (int j = 0; j < 32; j++) {
            float tv = 0.f;
            int addr = (j < k) ? (kb + j) : j;
            if (j <= k) tv = Lr[addr];
            Lk[j] = tv;
        }

        float* Po = out + (b0 + (size_t)s) * 1024;
        #pragma unroll
        for (int i = 0; i < 32; i++) {
            float a = Qk[i];
            #pragma unroll
            for (int j = 0; j <= i; j++)
                a += __shfl_sync(0xffffffffu, Lk[j], i) * Lk[j];
            Po[i * 32 + k] = a;
        }
    }
}

extern "C" void kernel_launch(void* const* d_in, const int* in_sizes, int n_in,
                              void* d_out, int out_size) {
    const float* P_prev = (const float*)d_in[0];
    const float* W1 = (const float*)d_in[1];
    const float* b1 = (const float*)d_in[2];
    const float* W2 = (const float*)d_in[3];
    const float* b2 = (const float*)d_in[4];
    const float* W3 = (const float*)d_in[5];
    const float* b3 = (const float*)d_in[6];
    const float* Q  = (const float*)d_in[7];
    float* out = (float*)d_out;

    const int B = in_sizes[0] / (NXD * NXD);   // 65536
    const int grid1 = B / BM;                  // 2048
    const int grid2 = B / 32;                  // 2048

    cudaFuncSetAttribute(covnet_mlp_kernel,
                         cudaFuncAttributeMaxDynamicSharedMemorySize,
                         SMEM1_FLOATS * sizeof(float));
    cudaFuncSetAttribute(covnet_llt_kernel,
                         cudaFuncAttributeMaxDynamicSharedMemorySize,
                         SMEM2_FLOATS * sizeof(float));

    covnet_mlp_kernel<<<grid1, NTHREADS, SMEM1_FLOATS * sizeof(float)>>>(
        P_prev, W1, b1, W2, b2, W3, b3);
    covnet_llt_kernel<<<grid2, NTHREADS, SMEM2_FLOATS * sizeof(float)>>>(Q, out);
}

// round 16
// speedup vs baseline: 1.0413x; 1.0413x over previous
#include <cuda_runtime.h>
#include <math.h>

#define NXD 32
#define HID 256
#define NOUT 528
#define BM 32
#define NTHREADS 128
#define HSTR 32
#define PSTR 1056           // pair row: 528 cols x 2 samples

// kernel-1 shared layout (float offsets), total 18432 floats = 73728 B -> 3 blocks/SM
#define OFF_H2 0        // 256*32 = 8192  (X overlays first 1024 floats)
#define OFF_X  0
#define OFF_W  8192     // 8*256 = 2048
#define OFF_H1 10240    // 256*32 = 8192
#define SMEM1_FLOATS 18432

// kernel-2: 16 pairs x 1056 = 16896 floats = 67584 B -> 3 blocks/SM
#define SMEM2_FLOATS (16 * PSTR)

// global scratch for pair-packed L: 32768 pairs x 1056 floats = 138.4 MB
__device__ float g_L[32768ull * PSTR];

typedef unsigned long long u64;

__device__ __forceinline__ u64 pk2(float lo, float hi) {
    u64 d; asm("mov.b64 %0, {%1, %2};" : "=l"(d) : "f"(lo), "f"(hi)); return d;
}
__device__ __forceinline__ void fma2(u64& d, u64 a, u64 b) {
    asm("fma.rn.f32x2 %0, %1, %2, %0;" : "+l"(d) : "l"(a), "l"(b));
}
__device__ __forceinline__ float2 up2(u64 d) {
    float2 r; asm("mov.b64 {%0, %1}, %2;" : "=f"(r.x), "=f"(r.y) : "l"(d)); return r;
}
__device__ __forceinline__ float ftanh(float x) {
    x = fminf(fmaxf(x, -15.f), 15.f);
    float e = __expf(2.f * x);
    return __fdividef(e - 1.f, e + 1.f);
}
__device__ __forceinline__ float fsplus(float v) {
    float sp = (v > 20.f) ? v : __logf(1.f + __expf(v));
    return fminf(fmaxf(sp + 0.01f, 0.01f), 100.f);
}

// Block 32s x 256c, 4 warps. Warp wp owns cols {64wp + c + 8t : t=0..7}.
// Lane (r=tx>>3, c=tx&7): samples sbase=8r..8r+7 ; cols cb=64wp+c, stride 8.
// MODE 0: tanh -> transposed smem outp[col*HSTR + s]   (h1/h2)
// MODE 1: G3 cols [0,256): wp==0 && t<4 -> softplus else 0.1*tanh -> pair-packed Lg
// MODE 2: G3 cols [256,512): 0.1*tanh -> pair-packed Lg (+256 col offset)
template<int KTOT, int MODE>
__device__ __forceinline__ void gemm_tile(
    float* sm, const float* __restrict__ Wg, int ldw,
    const float* __restrict__ bias,
    const float* sHin, float* outp,
    int sbase, int wp, int tx)
{
    const int NCH = KTOT / 8;
    const int c  = tx & 7;
    const int cb = 64 * wp + c;
    const int tid = threadIdx.x;
    float* sW = sm + OFF_W;

    u64 acc[4][8];
    #pragma unroll
    for (int t = 0; t < 8; t++) {
        float bv = __ldg(&bias[cb + 8 * t]);
        u64 bd = pk2(bv, bv);
        #pragma unroll
        for (int sp = 0; sp < 4; sp++) acc[sp][t] = bd;
    }

    float4 rg[4];
    auto stage_ld = [&](int ch) {
        #pragma unroll
        for (int rep = 0; rep < 4; rep++) {
            int idx = tid + 128 * rep;
            int row = idx >> 6, c4 = idx & 63;
            rg[rep] = *(const float4*)&Wg[(size_t)(ch * 8 + row) * ldw + 4 * c4];
        }
    };
    auto stage_st = [&]() {
        #pragma unroll
        for (int rep = 0; rep < 4; rep++) {
            int idx = tid + 128 * rep;
            int row = idx >> 6, c4 = idx & 63;
            *(float4*)&sW[row * 256 + 4 * c4] = rg[rep];
        }
    };

    stage_ld(0);
    stage_st();
    __syncthreads();

    for (int ch = 0; ch < NCH; ch++) {
        if (ch + 1 < NCH) stage_ld(ch + 1);
        #pragma unroll
        for (int kk = 0; kk < 8; kk++) {
            const float* hrow = sHin + (8 * ch + kk) * HSTR + sbase;
            ulonglong2 hA = *(const ulonglong2*)hrow;
            ulonglong2 hB = *(const ulonglong2*)(hrow + 4);
            u64 hd0 = hA.x, hd1 = hA.y, hd2 = hB.x, hd3 = hB.y;
            const float* wrow = sW + kk * 256;
            #pragma unroll
            for (int t = 0; t < 8; t++) {
                float wv = wrow[cb + 8 * t];
                u64 wd = pk2(wv, wv);
                fma2(acc[0][t], hd0, wd);
                fma2(acc[1][t], hd1, wd);
                fma2(acc[2][t], hd2, wd);
                fma2(acc[3][t], hd3, wd);
            }
        }
        __syncthreads();
        if (ch + 1 < NCH) { stage_st(); __syncthreads(); }
    }

    // epilogue
    if (MODE == 0) {
        #pragma unroll
        for (int t = 0; t < 8; t++) {
            const int col = cb + 8 * t;
            #pragma unroll
            for (int sp = 0; sp < 4; sp++) {
                float2 v = up2(acc[sp][t]);
                float2 o = { ftanh(v.x), ftanh(v.y) };
                *(float2*)&outp[col * HSTR + sbase + 2 * sp] = o;
            }
        }
    } else {
        // pair-packed store: Lg[(s>>1)*PSTR + 2*col + (s&1)]
        #pragma unroll
        for (int sp = 0; sp < 4; sp++) {
            #pragma unroll
            for (int e = 0; e < 2; e++) {
                const int s = sbase + 2 * sp + e;
                float* Ls = outp + (size_t)(s >> 1) * PSTR + (s & 1)
                          + 2 * ((MODE == 2) ? 256 : 0);
                #pragma unroll
                for (int t = 0; t < 8; t++) {
                    float2 v = up2(acc[sp][t]);
                    float val = e ? v.y : v.x;
                    bool dg = (MODE == 1) && (wp == 0) && (t < 4); // global col < 32
                    Ls[2 * (cb + 8 * t)] = dg ? fsplus(val) : 0.1f * ftanh(val);
                }
            }
        }
    }
}

__global__ void __launch_bounds__(NTHREADS, 3) covnet_mlp_kernel(
    const float* __restrict__ P_prev,
    const float* __restrict__ W1, const float* __restrict__ b1,
    const float* __restrict__ W2, const float* __restrict__ b2,
    const float* __restrict__ W3, const float* __restrict__ b3)
{
    extern __shared__ float sm[];
    const int tid = threadIdx.x;
    const int tx = tid & 31;
    const int wp = tid >> 5;            // 0..3
    const int sbase = 8 * (tx >> 3);
    const size_t b0 = (size_t)blockIdx.x * BM;
    float* Lg = g_L + (b0 >> 1) * PSTR;

    // gather diagonal (transposed): sX[d*HSTR + s] = log(clip(P_prev[s,d,d]))
    for (int i = tid; i < NXD * BM; i += NTHREADS) {
        int d = i >> 5, s = i & 31;
        float v = P_prev[(b0 + (size_t)s) * 1024 + d * 33];
        sm[OFF_X + d * HSTR + s] = __logf(fmaxf(v, 1e-6f));
    }
    __syncthreads();

    gemm_tile<32,  0>(sm, W1,       HID,  b1,       sm + OFF_X,  sm + OFF_H1, sbase, wp, tx);
    gemm_tile<256, 0>(sm, W2,       HID,  b2,       sm + OFF_H1, sm + OFF_H2, sbase, wp, tx);
    gemm_tile<256, 1>(sm, W3,       NOUT, b3,       sm + OFF_H2, Lg,          sbase, wp, tx);
    gemm_tile<256, 2>(sm, W3 + 256, NOUT, b3 + 256, sm + OFF_H2, Lg,          sbase, wp, tx);

    // ====== GEMM3 tail: cols [512, 528) — lane s=tx, warp wp -> cols 512+4wp..+3
    {
        const int s = tx;
        float a[4];
        float4 bt = *(const float4*)&b3[512 + 4 * wp];
        a[0] = bt.x; a[1] = bt.y; a[2] = bt.z; a[3] = bt.w;
        const float* hr = sm + OFF_H2;
        #pragma unroll 8
        for (int k = 0; k < HID; k++) {
            float hv = hr[k * HSTR + s];
            float4 w = __ldg((const float4*)&W3[(size_t)k * NOUT + 512 + 4 * wp]);
            a[0] += hv * w.x; a[1] += hv * w.y;
            a[2] += hv * w.z; a[3] += hv * w.w;
        }
        float* Ls = Lg + (size_t)(s >> 1) * PSTR + (s & 1) + 2 * (512 + 4 * wp);
        #pragma unroll
        for (int q = 0; q < 4; q++) Ls[2 * q] = 0.1f * ftanh(a[q]);
    }
}

// =================== kernel 2: P = L*L^T + Q (pair-packed, f32x2) ============
__global__ void __launch_bounds__(NTHREADS, 3) covnet_llt_kernel(
    const float* __restrict__ Q, float* __restrict__ out)
{
    extern __shared__ float sm[];   // 16 pairs x PSTR
    const int tid = threadIdx.x;
    const int tx = tid & 31;
    const int wp = tid >> 5;
    const size_t p0 = (size_t)blockIdx.x * 16;      // first pair of block

    // coalesced load of 16 pair-rows
    {
        const float4* src = (const float4*)(g_L + p0 * PSTR);
        #pragma unroll 4
        for (int idx = tid; idx < 16 * PSTR / 4; idx += NTHREADS)
            *(float4*)&sm[4 * idx] = src[idx];
    }
    __syncthreads();

    const int k = tx;
    float Qk[32];
    #pragma unroll
    for (int i = 0; i < 32; i++) Qk[i] = __ldg(&Q[i * 32 + k]);
    const int kb = 32 + k * (k - 1) / 2;

    // warp wp handles pairs 4wp..4wp+3
    #pragma unroll 1
    for (int pp = 0; pp < 4; pp++) {
        const int p = 4 * wp + pp;
        const float* Lr = sm + p * PSTR;

        // gather row k for both samples of the pair: Lk2[j] = (Ls0[k][j], Ls1[k][j])
        u64 Lk2[32];
        #pragma unroll
        for (int j = 0; j < 32; j++) {
            u64 tv = 0;
            int addr = (j < k) ? (kb + j) : j;    // packed index: lower or diagonal
            if (j <= k) tv = *(const u64*)&Lr[2 * addr];
            Lk2[j] = tv;
        }

        float* Po0 = out + (2 * (p0 + p)) * 1024ull;
        float* Po1 = Po0 + 1024;
        #pragma unroll
        for (int i = 0; i < 32; i++) {
            u64 a2 = pk2(Qk[i], Qk[i]);
            const int ib = 32 + i * (i - 1) / 2;
            #pragma unroll
            for (int j = 0; j < i; j++)           // strictly lower entries of row i
                fma2(a2, *(const u64*)&Lr[2 * (ib + j)], Lk2[j]);
            fma2(a2, *(const u64*)&Lr[2 * i], Lk2[i]);   // diagonal term
            float2 v = up2(a2);
            Po0[i * 32 + k] = v.x;
            Po1[i * 32 + k] = v.y;
        }
    }
}

extern "C" void kernel_launch(void* const* d_in, const int* in_sizes, int n_in,
                              void* d_out, int out_size) {
    const float* P_prev = (const float*)d_in[0];
    const float* W1 = (const float*)d_in[1];
    const float* b1 = (const float*)d_in[2];
    const float* W2 = (const float*)d_in[3];
    const float* b2 = (const float*)d_in[4];
    const float* W3 = (const float*)d_in[5];
    const float* b3 = (const float*)d_in[6];
    const float* Q  = (const float*)d_in[7];
    float* out = (float*)d_out;

    const int B = in_sizes[0] / (NXD * NXD);   // 65536
    const int grid1 = B / BM;                  // 2048
    const int grid2 = B / 32;                  // 2048 (16 pairs per block)

    cudaFuncSetAttribute(covnet_mlp_kernel,
                         cudaFuncAttributeMaxDynamicSharedMemorySize,
                         SMEM1_FLOATS * sizeof(float));
    cudaFuncSetAttribute(covnet_llt_kernel,
                         cudaFuncAttributeMaxDynamicSharedMemorySize,
                         SMEM2_FLOATS * sizeof(float));

    covnet_mlp_kernel<<<grid1, NTHREADS, SMEM1_FLOATS * sizeof(float)>>>(
        P_prev, W1, b1, W2, b2, W3, b3);
    covnet_llt_kernel<<<grid2, NTHREADS, SMEM2_FLOATS * sizeof(float)>>>(Q, out);
}